// round 5
// baseline (speedup 1.0000x reference)
#include <cuda_runtime.h>
#include <math.h>

#define LNUM   102
#define LSTART 100               // start label = L-2
#define LPAD   104               // q vector length (2 pad entries, always 0)
#define HALF   52                // K-entries per thread-half
#define NT     256
#define MAXB   1024

__device__ int g_perm[MAXB];
typedef unsigned long long ull;

// ---------- packed f32x2 helpers ----------
__device__ __forceinline__ void fma2(ull& d, ull a, ull b) {
    asm("fma.rn.f32x2 %0, %1, %2, %0;" : "+l"(d) : "l"(a), "l"(b));
}
__device__ __forceinline__ ull add2(ull a, ull b) {
    ull r; asm("add.rn.f32x2 %0, %1, %2;" : "=l"(r) : "l"(a), "l"(b)); return r;
}
__device__ __forceinline__ float2 unpack2(ull u) {
    float2 f; asm("mov.b64 {%0, %1}, %2;" : "=f"(f.x), "=f"(f.y) : "l"(u)); return f;
}
__device__ __forceinline__ ull pack2(float x, float y) {
    ull u; asm("mov.b64 %0, {%1, %2};" : "=l"(u) : "f"(x), "f"(y)); return u;
}

// ---------- LPT pre-sort: order batches by descending length ----------
__global__ void sort_kernel(const int* __restrict__ lens, int B) {
    __shared__ int keys[MAXB];
    const int tid = threadIdx.x;
    for (int i = tid; i < MAXB; i += blockDim.x)
        keys[i] = (i < B) ? ((lens[i] << 10) | (MAXB - 1 - i)) : -1;
    __syncthreads();
    for (int k = 2; k <= MAXB; k <<= 1) {
        for (int j = k >> 1; j > 0; j >>= 1) {
            for (int i = tid; i < MAXB; i += blockDim.x) {
                int ixj = i ^ j;
                if (ixj > i) {
                    int a = keys[i], c = keys[ixj];
                    bool seg = ((i & k) == 0);   // descending
                    if (seg ? (a < c) : (a > c)) { keys[i] = c; keys[ixj] = a; }
                }
            }
            __syncthreads();
        }
    }
    for (int i = tid; i < B; i += blockDim.x)
        g_perm[i] = (MAXB - 1) - (keys[i] & (MAXB - 1));
}

// ---------- CRF forward: split-K over 256 threads, linear domain ----------
__global__ __launch_bounds__(NT, 3)
void crf_fwd_kernel(const float* __restrict__ logits,
                    const float* __restrict__ trans,
                    const int*   __restrict__ lens,
                    float* __restrict__ out,
                    int T)
{
    const int tid = threadIdx.x;
    const int h   = tid >> 7;          // K-half: 0 or 1
    const int j   = tid & 127;         // output label (j < LPAD active)
    const int b   = g_perm[blockIdx.x];

    __shared__ __align__(16) float q_sh[2][LPAD];
    __shared__ float sh_part[2][128];
    __shared__ float sh_hmax[2];
    __shared__ float red[8];

    // E2[m] = exp(trans[j, HALF*h + 2m .. +1]) — 26 packed pairs (pads = 0)
    ull E2[HALF / 2];
    #pragma unroll
    for (int m = 0; m < HALF / 2; ++m) {
        float a = 0.f, c = 0.f;
        const int k = HALF * h + 2 * m;
        if (j < LNUM) {
            const float* tr = trans + (size_t)j * LNUM;
            if (k + 0 < LNUM) a = __expf(tr[k + 0]);
            if (k + 1 < LNUM) c = __expf(tr[k + 1]);
        }
        E2[m] = pack2(a, c);
    }

    // init: q = exp(alpha0) — 1 at start label, 0 elsewhere
    if (tid < LPAD) q_sh[0][tid] = (tid == LSTART) ? 1.f : 0.f;
    float q = (j == LSTART) ? 1.f : 0.f;   // live copy for the final reduce

    int len = lens[b];
    if (len > T) len = T;
    const float* lg = logits + (size_t)b * T * LNUM;

    float C = 0.f;

    // depth-4 logit pipeline
    float lgq[4];
    #pragma unroll
    for (int u = 0; u < 4; ++u)
        lgq[u] = (u < len && j < LNUM) ? lg[(size_t)u * LNUM + j] : 0.f;

    __syncthreads();

    for (int tc = 0; tc < len; tc += 4) {
        // prefetch next chunk (MLP=4 covers DRAM latency)
        float lgn[4];
        #pragma unroll
        for (int u = 0; u < 4; ++u) {
            const int tl = tc + 4 + u;
            lgn[u] = (tl < len && j < LNUM) ? lg[(size_t)tl * LNUM + j] : 0.f;
        }

        #pragma unroll
        for (int u = 0; u < 4; ++u) {
            const int t = tc + u;
            if (t >= len) break;                   // uniform across block

            const float el = __expf(lgq[u]);

            // partial[j] over this thread's K-half: 13 LDS.128 + 26 FMA2
            ull a0 = 0ull, a1 = 0ull, a2 = 0ull, a3 = 0ull;
            float m0 = 0.f, m1 = 0.f;
            const ulonglong2* ps =
                reinterpret_cast<const ulonglong2*>(&q_sh[u & 1][HALF * h]);
            #pragma unroll
            for (int m = 0; m < HALF / 4; ++m) {
                ulonglong2 v = ps[m];
                if (m & 1) { fma2(a2, E2[2 * m], v.x); fma2(a3, E2[2 * m + 1], v.y); }
                else       { fma2(a0, E2[2 * m], v.x); fma2(a1, E2[2 * m + 1], v.y); }
                if (u == 0) {                      // fold half-max (ALU pipe)
                    float2 fx = unpack2(v.x), fy = unpack2(v.y);
                    m0 = fmaxf(m0, fmaxf(fx.x, fx.y));
                    m1 = fmaxf(m1, fmaxf(fy.x, fy.y));
                }
            }
            float2 fs = unpack2(add2(add2(a0, a1), add2(a2, a3)));
            const float p = fs.x + fs.y;

            sh_part[h][j] = p;
            if (u == 0 && j == 0) sh_hmax[h] = fmaxf(m0, m1);
            __syncthreads();                       // exchange barrier

            float y = p + sh_part[h ^ 1][j];
            if (u == 0 && t > 0) {                 // uniform renorm every 4 steps
                const float M = fmaxf(fmaxf(sh_hmax[0], sh_hmax[1]), 1e-30f);
                y *= __fdividef(1.f, M);
                C += __logf(M);
            }
            q = el * y;                            // both halves redundantly
            if (h == 0 && j < LPAD) q_sh[(u + 1) & 1][j] = q;
            __syncthreads();                       // publish barrier
        }

        #pragma unroll
        for (int u = 0; u < 4; ++u) lgq[u] = lgn[u];
    }

    // out[b] = C + log( sum_j q[j] * exp(trans[stop, j]) )
    float v = (h == 0 && j < LNUM)
        ? q * __expf(trans[(size_t)(LNUM - 1) * LNUM + j]) : 0.f;
    #pragma unroll
    for (int o = 16; o; o >>= 1)
        v += __shfl_xor_sync(0xffffffffu, v, o);
    if ((tid & 31) == 0) red[tid >> 5] = v;
    __syncthreads();
    if (tid == 0) {
        float s = ((red[0] + red[1]) + (red[2] + red[3]))
                + ((red[4] + red[5]) + (red[6] + red[7]));
        out[b] = C + logf(s);
    }
}

extern "C" void kernel_launch(void* const* d_in, const int* in_sizes, int n_in,
                              void* d_out, int out_size)
{
    const float* logits = (const float*)d_in[0];   // [B, T, L] f32
    const float* trans  = (const float*)d_in[1];   // [L, L]    f32
    const int*   lens   = (const int*)d_in[2];     // [B]       i32
    float*       out    = (float*)d_out;           // [B]       f32

    const int B = in_sizes[2];
    const int T = in_sizes[0] / (B * LNUM);

    sort_kernel<<<1, MAXB>>>(lens, B);
    crf_fwd_kernel<<<B, NT>>>(logits, trans, lens, out, T);
}